// round 1
// baseline (speedup 1.0000x reference)
#include <cuda_runtime.h>

// ProgressiveFocusedAttention — R0 fp32 baseline.
// 3-kernel pipeline:
//   K1 qkv_kernel      : shifted-window gather + QKV GEMM (64x768, K=256) per window
//   K2 attn_kernel     : per (window, head): S=QK^T, (S*scale+mask)*prev, softmax,
//                        write attn to d_out, O = P@V to scratch
//   K3 lepe_proj_kernel: LePE depthwise 3x3 (window-local SAME) + O, proj GEMM
//                        (64x256, K=256), window-reverse + unshift scatter to d_out.
//
// d_out = concat(out.flatten() [33554432 f32], attn.flatten() [67108864 f32]).

#define B_    8
#define H_    128
#define W_    128
#define C_    256
#define HEADS 8
#define WS_   8
#define SHIFT 4
#define HD    32
#define L_    64
#define NW_   256
#define NWIN  2048
#define SCALE 0.17677669529663687f

#define OUT_ELEMS (B_*H_*W_*C_)            // 33554432

// Scratch (allocation-free rule: __device__ globals)
__device__ float g_q[NWIN*HEADS*L_*HD];
__device__ float g_k[NWIN*HEADS*L_*HD];
__device__ float g_v[NWIN*HEADS*L_*HD];
__device__ float g_o[NWIN*L_*C_];

// ---------------------------------------------------------------------------
// Kernel 1: QKV projection. One block per window. 256 threads.
// smem: A = x window transposed [K=256][64+pad1]  (scalar a-loads, conflict-free)
//       Bs = weight chunk       [K=256][64]       (float4 b-loads)
// Each thread computes a 4x4 micro-tile of a 64x64 output chunk (12 chunks).
// ---------------------------------------------------------------------------
__global__ __launch_bounds__(256, 1) void qkv_kernel(
    const float* __restrict__ x, const float* __restrict__ qkv_w,
    const float* __restrict__ qkv_b) {
  extern __shared__ float sm[];
  float* A  = sm;             // 256*65
  float* Bs = sm + 256*65;    // 256*64
  const int n = blockIdx.x, t = threadIdx.x;
  const int b = n >> 8, wi = n & 255, wh = wi >> 4, ww = wi & 15;

  // Gather cyclically-shifted window, store transposed A[k][l]
  const float4* x4 = reinterpret_cast<const float4*>(x);
  #pragma unroll
  for (int it = 0; it < 16; ++it) {
    int f  = it * 256 + t;          // 4096 float4 = 64 rows * 64 f4
    int l  = f >> 6, c4 = f & 63;
    int r  = l >> 3, cc = l & 7;
    int hh = (wh * WS_ + r  + SHIFT) & 127;
    int wp = (ww * WS_ + cc + SHIFT) & 127;
    float4 v = x4[((b * H_ + hh) * W_ + wp) * (C_ / 4) + c4];
    int cb = c4 * 4;
    A[(cb + 0) * 65 + l] = v.x;
    A[(cb + 1) * 65 + l] = v.y;
    A[(cb + 2) * 65 + l] = v.z;
    A[(cb + 3) * 65 + l] = v.w;
  }
  __syncthreads();

  const int ty = t >> 4, tx = t & 15;
  const float4* w4 = reinterpret_cast<const float4*>(qkv_w);

  for (int ch = 0; ch < 12; ++ch) {
    // load 256x64 weight chunk
    #pragma unroll
    for (int it = 0; it < 16; ++it) {
      int f = it * 256 + t;          // 4096 f4
      int k = f >> 4, j4 = f & 15;
      *reinterpret_cast<float4*>(&Bs[k * 64 + j4 * 4]) = w4[k * 192 + ch * 16 + j4];
    }
    __syncthreads();

    float acc[4][4];
    #pragma unroll
    for (int i = 0; i < 4; ++i)
      #pragma unroll
      for (int j = 0; j < 4; ++j) acc[i][j] = 0.f;

    #pragma unroll 8
    for (int k = 0; k < 256; ++k) {
      float a[4];
      #pragma unroll
      for (int i = 0; i < 4; ++i) a[i] = A[k * 65 + ty * 4 + i];
      float4 bv = *reinterpret_cast<const float4*>(&Bs[k * 64 + tx * 4]);
      float bb[4] = {bv.x, bv.y, bv.z, bv.w};
      #pragma unroll
      for (int i = 0; i < 4; ++i)
        #pragma unroll
        for (int j = 0; j < 4; ++j) acc[i][j] += a[i] * bb[j];
    }
    __syncthreads();  // guard Bs before next chunk's writes

    const int cg0   = ch * 64 + tx * 4;
    const int which = cg0 >> 8;          // chunk is entirely q, k, or v
    const int cc0   = cg0 & 255;
    const int head  = cc0 >> 5, d0 = cc0 & 31;
    float* buf = (which == 0) ? g_q : (which == 1) ? g_k : g_v;
    const float b0 = qkv_b[cg0 + 0], b1 = qkv_b[cg0 + 1];
    const float b2 = qkv_b[cg0 + 2], b3 = qkv_b[cg0 + 3];
    #pragma unroll
    for (int i = 0; i < 4; ++i) {
      int l = ty * 4 + i;
      float4 o = make_float4(acc[i][0] + b0, acc[i][1] + b1,
                             acc[i][2] + b2, acc[i][3] + b3);
      *reinterpret_cast<float4*>(&buf[((n * HEADS + head) * L_ + l) * HD + d0]) = o;
    }
  }
}

// ---------------------------------------------------------------------------
// Kernel 2: attention per (window, head). 128 threads (4 warps).
// S = QK^T (raw), then warp-per-row: val = fmaf(s,SCALE,mask)*prev, softmax,
// write attn; then O = P @ V.
// ---------------------------------------------------------------------------
__global__ __launch_bounds__(128) void attn_kernel(
    const float* __restrict__ prev, float* __restrict__ attn_out) {
  __shared__ float qs[64 * 33], ks[64 * 33], vs[64 * 33];
  __shared__ float ss[64 * 65];
  __shared__ int   rid[64];
  const int n = blockIdx.x, h = blockIdx.y, t = threadIdx.x;
  const int wi = n & 255, wh = wi >> 4, ww = wi & 15;
  const int base = (n * HEADS + h) * L_ * HD;

  const float4* q4 = reinterpret_cast<const float4*>(g_q + base);
  const float4* k4 = reinterpret_cast<const float4*>(g_k + base);
  const float4* v4 = reinterpret_cast<const float4*>(g_v + base);
  #pragma unroll
  for (int it = 0; it < 4; ++it) {
    int f = it * 128 + t;           // 512 f4
    int l = f >> 3, d = (f & 7) * 4;
    float4 a = q4[f], bq = k4[f], c = v4[f];
    qs[l*33+d] = a.x;  qs[l*33+d+1] = a.y;  qs[l*33+d+2] = a.z;  qs[l*33+d+3] = a.w;
    ks[l*33+d] = bq.x; ks[l*33+d+1] = bq.y; ks[l*33+d+2] = bq.z; ks[l*33+d+3] = bq.w;
    vs[l*33+d] = c.x;  vs[l*33+d+1] = c.y;  vs[l*33+d+2] = c.z;  vs[l*33+d+3] = c.w;
  }
  if (t < 64) {
    int r = t >> 3, c = t & 7;
    int hs = wh * WS_ + r, wsp = ww * WS_ + c;
    int ih = (hs  < 120) ? 0 : ((hs  < 124) ? 1 : 2);
    int iw = (wsp < 120) ? 0 : ((wsp < 124) ? 1 : 2);
    rid[t] = ih * 3 + iw;
  }
  __syncthreads();

  const int ry = t >> 3, cx = t & 7;  // 16x8 thread grid
  {
    float acc[4][8];
    #pragma unroll
    for (int i = 0; i < 4; ++i)
      #pragma unroll
      for (int j = 0; j < 8; ++j) acc[i][j] = 0.f;
    #pragma unroll 4
    for (int d = 0; d < 32; ++d) {
      float a[4], bb[8];
      #pragma unroll
      for (int i = 0; i < 4; ++i) a[i] = qs[(ry * 4 + i) * 33 + d];
      #pragma unroll
      for (int j = 0; j < 8; ++j) bb[j] = ks[(cx * 8 + j) * 33 + d];
      #pragma unroll
      for (int i = 0; i < 4; ++i)
        #pragma unroll
        for (int j = 0; j < 8; ++j) acc[i][j] += a[i] * bb[j];
    }
    #pragma unroll
    for (int i = 0; i < 4; ++i)
      #pragma unroll
      for (int j = 0; j < 8; ++j)
        ss[(ry * 4 + i) * 65 + cx * 8 + j] = acc[i][j];
  }
  __syncthreads();

  // softmax: warp per row, 2 cols per lane
  const int warp = t >> 5, lane = t & 31;
  const float* pb = prev + (size_t)(n * HEADS + h) * 4096;
  float* ab = attn_out ? attn_out + (size_t)(n * HEADS + h) * 4096 : nullptr;
  const int idk0 = rid[lane], idk1 = rid[lane + 32];
  for (int rr = 0; rr < 16; ++rr) {
    int row = warp * 16 + rr;
    int idq = rid[row];
    float v0 = ss[row * 65 + lane];
    float v1 = ss[row * 65 + lane + 32];
    v0 = fmaf(v0, SCALE, (idq == idk0) ? 0.f : -100.f) * pb[row * 64 + lane];
    v1 = fmaf(v1, SCALE, (idq == idk1) ? 0.f : -100.f) * pb[row * 64 + lane + 32];
    float mx = fmaxf(v0, v1);
    #pragma unroll
    for (int o = 16; o >= 1; o >>= 1) mx = fmaxf(mx, __shfl_xor_sync(0xffffffffu, mx, o));
    float e0 = __expf(v0 - mx), e1 = __expf(v1 - mx);
    float sum = e0 + e1;
    #pragma unroll
    for (int o = 16; o >= 1; o >>= 1) sum += __shfl_xor_sync(0xffffffffu, sum, o);
    float inv = 1.f / sum;
    e0 *= inv; e1 *= inv;
    ss[row * 65 + lane]      = e0;
    ss[row * 65 + lane + 32] = e1;
    if (ab) { ab[row * 64 + lane] = e0; ab[row * 64 + lane + 32] = e1; }
  }
  __syncthreads();

  // O = P @ V  (64x32, K=64); thread: 4 rows x 4 d
  {
    float acc[4][4];
    #pragma unroll
    for (int i = 0; i < 4; ++i)
      #pragma unroll
      for (int j = 0; j < 4; ++j) acc[i][j] = 0.f;
    #pragma unroll 4
    for (int kk = 0; kk < 64; ++kk) {
      float p[4], vv[4];
      #pragma unroll
      for (int i = 0; i < 4; ++i) p[i] = ss[(ry * 4 + i) * 65 + kk];
      #pragma unroll
      for (int j = 0; j < 4; ++j) vv[j] = vs[kk * 33 + cx * 4 + j];
      #pragma unroll
      for (int i = 0; i < 4; ++i)
        #pragma unroll
        for (int j = 0; j < 4; ++j) acc[i][j] += p[i] * vv[j];
    }
    #pragma unroll
    for (int i = 0; i < 4; ++i) {
      int l = ry * 4 + i;
      *reinterpret_cast<float4*>(&g_o[(n * L_ + l) * C_ + h * HD + cx * 4]) =
          make_float4(acc[i][0], acc[i][1], acc[i][2], acc[i][3]);
    }
  }
}

// ---------------------------------------------------------------------------
// Kernel 3: LePE + O, proj GEMM, window-reverse + unshift scatter.
// One block per window, 256 threads.
// ---------------------------------------------------------------------------
__global__ __launch_bounds__(256, 1) void lepe_proj_kernel(
    const float* __restrict__ proj_w, const float* __restrict__ proj_b,
    const float* __restrict__ lepe_w, const float* __restrict__ lepe_b,
    float* __restrict__ out) {
  extern __shared__ float sm[];
  float* vsm = sm;                   // [64][256]
  float* A   = sm + 64 * 256;        // [256][65]  (o + lepe, transposed)
  float* Bs  = A + 256 * 65;         // [256][64]
  const int n = blockIdx.x, t = threadIdx.x;
  const int b = n >> 8, wi = n & 255, wh = wi >> 4, ww = wi & 15;

  // V window into [l][c]
  const float4* v4 = reinterpret_cast<const float4*>(g_v + n * HEADS * L_ * HD);
  #pragma unroll
  for (int it = 0; it < 16; ++it) {
    int f = it * 256 + t;            // 4096 f4, [h][l][d4]
    int hh = f >> 9, rem = f & 511;
    int l = rem >> 3, d4 = rem & 7;
    *reinterpret_cast<float4*>(&vsm[l * C_ + hh * HD + d4 * 4]) = v4[f];
  }
  __syncthreads();

  // lepe (3x3 depthwise, window-local SAME) + o  -> A[c][l]
  {
    const int c = t;
    float w9[9];
    #pragma unroll
    for (int i = 0; i < 9; ++i) w9[i] = lepe_w[i * C_ + c];
    const float bl = lepe_b[c];
    const float* ob = g_o + n * L_ * C_;
    for (int l = 0; l < 64; ++l) {
      int r = l >> 3, cc = l & 7;
      float s = ob[l * C_ + c] + bl;
      #pragma unroll
      for (int dr = 0; dr < 3; ++dr) {
        int rr = r + dr - 1;
        if (rr < 0 || rr > 7) continue;
        #pragma unroll
        for (int dc = 0; dc < 3; ++dc) {
          int c2 = cc + dc - 1;
          if (c2 < 0 || c2 > 7) continue;
          s += w9[dr * 3 + dc] * vsm[(rr * 8 + c2) * C_ + c];
        }
      }
      A[c * 65 + l] = s;
    }
  }
  __syncthreads();

  // proj GEMM: 64x256, K=256, 4 chunks of 64 cols
  const int ty = t >> 4, tx = t & 15;
  const float4* pw4 = reinterpret_cast<const float4*>(proj_w);
  for (int ch = 0; ch < 4; ++ch) {
    #pragma unroll
    for (int it = 0; it < 16; ++it) {
      int f = it * 256 + t;
      int k = f >> 4, j4 = f & 15;
      *reinterpret_cast<float4*>(&Bs[k * 64 + j4 * 4]) = pw4[k * 64 + ch * 16 + j4];
    }
    __syncthreads();

    float acc[4][4];
    #pragma unroll
    for (int i = 0; i < 4; ++i)
      #pragma unroll
      for (int j = 0; j < 4; ++j) acc[i][j] = 0.f;

    #pragma unroll 8
    for (int k = 0; k < 256; ++k) {
      float a[4];
      #pragma unroll
      for (int i = 0; i < 4; ++i) a[i] = A[k * 65 + ty * 4 + i];
      float4 bv = *reinterpret_cast<const float4*>(&Bs[k * 64 + tx * 4]);
      float bb[4] = {bv.x, bv.y, bv.z, bv.w};
      #pragma unroll
      for (int i = 0; i < 4; ++i)
        #pragma unroll
        for (int j = 0; j < 4; ++j) acc[i][j] += a[i] * bb[j];
    }
    __syncthreads();

    const int co0 = ch * 64 + tx * 4;
    const float b0 = proj_b[co0 + 0], b1 = proj_b[co0 + 1];
    const float b2 = proj_b[co0 + 2], b3 = proj_b[co0 + 3];
    #pragma unroll
    for (int i = 0; i < 4; ++i) {
      int l = ty * 4 + i;
      int r = l >> 3, cc = l & 7;
      int hh = (wh * WS_ + r  + SHIFT) & 127;
      int wp = (ww * WS_ + cc + SHIFT) & 127;
      *reinterpret_cast<float4*>(&out[((b * H_ + hh) * W_ + wp) * C_ + co0]) =
          make_float4(acc[i][0] + b0, acc[i][1] + b1, acc[i][2] + b2, acc[i][3] + b3);
    }
  }
}

// ---------------------------------------------------------------------------
extern "C" void kernel_launch(void* const* d_in, const int* in_sizes, int n_in,
                              void* d_out, int out_size) {
  const float* x      = (const float*)d_in[0];
  const float* prev   = (const float*)d_in[1];
  const float* qkv_w  = (const float*)d_in[2];
  const float* qkv_b  = (const float*)d_in[3];
  const float* proj_w = (const float*)d_in[4];
  const float* proj_b = (const float*)d_in[5];
  const float* lepe_w = (const float*)d_in[6];
  const float* lepe_b = (const float*)d_in[7];
  float* out  = (float*)d_out;
  float* attn = (out_size > OUT_ELEMS) ? out + OUT_ELEMS : nullptr;

  const int smem1 = (256 * 65 + 256 * 64) * 4;               // 132096
  const int smem3 = (64 * 256 + 256 * 65 + 256 * 64) * 4;    // 197632
  cudaFuncSetAttribute(qkv_kernel, cudaFuncAttributeMaxDynamicSharedMemorySize, smem1);
  cudaFuncSetAttribute(lepe_proj_kernel, cudaFuncAttributeMaxDynamicSharedMemorySize, smem3);

  qkv_kernel<<<NWIN, 256, smem1>>>(x, qkv_w, qkv_b);
  attn_kernel<<<dim3(NWIN, HEADS), 128>>>(prev, attn);
  lepe_proj_kernel<<<NWIN, 256, smem3>>>(proj_w, proj_b, lepe_w, lepe_b, out);
}

// round 2
// speedup vs baseline: 1.0001x; 1.0001x over previous
#include <cuda_runtime.h>

// ProgressiveFocusedAttention — R0 fp32 baseline.
// 3-kernel pipeline:
//   K1 qkv_kernel      : shifted-window gather + QKV GEMM (64x768, K=256) per window
//   K2 attn_kernel     : per (window, head): S=QK^T, (S*scale+mask)*prev, softmax,
//                        write attn to d_out, O = P@V to scratch
//   K3 lepe_proj_kernel: LePE depthwise 3x3 (window-local SAME) + O, proj GEMM
//                        (64x256, K=256), window-reverse + unshift scatter to d_out.
//
// d_out = concat(out.flatten() [33554432 f32], attn.flatten() [67108864 f32]).

#define B_    8
#define H_    128
#define W_    128
#define C_    256
#define HEADS 8
#define WS_   8
#define SHIFT 4
#define HD    32
#define L_    64
#define NW_   256
#define NWIN  2048
#define SCALE 0.17677669529663687f

#define OUT_ELEMS (B_*H_*W_*C_)            // 33554432

// Scratch (allocation-free rule: __device__ globals)
__device__ float g_q[NWIN*HEADS*L_*HD];
__device__ float g_k[NWIN*HEADS*L_*HD];
__device__ float g_v[NWIN*HEADS*L_*HD];
__device__ float g_o[NWIN*L_*C_];

// ---------------------------------------------------------------------------
// Kernel 1: QKV projection. One block per window. 256 threads.
// smem: A = x window transposed [K=256][64+pad1]  (scalar a-loads, conflict-free)
//       Bs = weight chunk       [K=256][64]       (float4 b-loads)
// Each thread computes a 4x4 micro-tile of a 64x64 output chunk (12 chunks).
// ---------------------------------------------------------------------------
__global__ __launch_bounds__(256, 1) void qkv_kernel(
    const float* __restrict__ x, const float* __restrict__ qkv_w,
    const float* __restrict__ qkv_b) {
  extern __shared__ float sm[];
  float* A  = sm;             // 256*65
  float* Bs = sm + 256*65;    // 256*64
  const int n = blockIdx.x, t = threadIdx.x;
  const int b = n >> 8, wi = n & 255, wh = wi >> 4, ww = wi & 15;

  // Gather cyclically-shifted window, store transposed A[k][l]
  const float4* x4 = reinterpret_cast<const float4*>(x);
  #pragma unroll
  for (int it = 0; it < 16; ++it) {
    int f  = it * 256 + t;          // 4096 float4 = 64 rows * 64 f4
    int l  = f >> 6, c4 = f & 63;
    int r  = l >> 3, cc = l & 7;
    int hh = (wh * WS_ + r  + SHIFT) & 127;
    int wp = (ww * WS_ + cc + SHIFT) & 127;
    float4 v = x4[((b * H_ + hh) * W_ + wp) * (C_ / 4) + c4];
    int cb = c4 * 4;
    A[(cb + 0) * 65 + l] = v.x;
    A[(cb + 1) * 65 + l] = v.y;
    A[(cb + 2) * 65 + l] = v.z;
    A[(cb + 3) * 65 + l] = v.w;
  }
  __syncthreads();

  const int ty = t >> 4, tx = t & 15;
  const float4* w4 = reinterpret_cast<const float4*>(qkv_w);

  for (int ch = 0; ch < 12; ++ch) {
    // load 256x64 weight chunk
    #pragma unroll
    for (int it = 0; it < 16; ++it) {
      int f = it * 256 + t;          // 4096 f4
      int k = f >> 4, j4 = f & 15;
      *reinterpret_cast<float4*>(&Bs[k * 64 + j4 * 4]) = w4[k * 192 + ch * 16 + j4];
    }
    __syncthreads();

    float acc[4][4];
    #pragma unroll
    for (int i = 0; i < 4; ++i)
      #pragma unroll
      for (int j = 0; j < 4; ++j) acc[i][j] = 0.f;

    #pragma unroll 8
    for (int k = 0; k < 256; ++k) {
      float a[4];
      #pragma unroll
      for (int i = 0; i < 4; ++i) a[i] = A[k * 65 + ty * 4 + i];
      float4 bv = *reinterpret_cast<const float4*>(&Bs[k * 64 + tx * 4]);
      float bb[4] = {bv.x, bv.y, bv.z, bv.w};
      #pragma unroll
      for (int i = 0; i < 4; ++i)
        #pragma unroll
        for (int j = 0; j < 4; ++j) acc[i][j] += a[i] * bb[j];
    }
    __syncthreads();  // guard Bs before next chunk's writes

    const int cg0   = ch * 64 + tx * 4;
    const int which = cg0 >> 8;          // chunk is entirely q, k, or v
    const int cc0   = cg0 & 255;
    const int head  = cc0 >> 5, d0 = cc0 & 31;
    float* buf = (which == 0) ? g_q : (which == 1) ? g_k : g_v;
    const float b0 = qkv_b[cg0 + 0], b1 = qkv_b[cg0 + 1];
    const float b2 = qkv_b[cg0 + 2], b3 = qkv_b[cg0 + 3];
    #pragma unroll
    for (int i = 0; i < 4; ++i) {
      int l = ty * 4 + i;
      float4 o = make_float4(acc[i][0] + b0, acc[i][1] + b1,
                             acc[i][2] + b2, acc[i][3] + b3);
      *reinterpret_cast<float4*>(&buf[((n * HEADS + head) * L_ + l) * HD + d0]) = o;
    }
  }
}

// ---------------------------------------------------------------------------
// Kernel 2: attention per (window, head). 128 threads (4 warps).
// S = QK^T (raw), then warp-per-row: val = fmaf(s,SCALE,mask)*prev, softmax,
// write attn; then O = P @ V.
// ---------------------------------------------------------------------------
__global__ __launch_bounds__(128) void attn_kernel(
    const float* __restrict__ prev, float* __restrict__ attn_out) {
  __shared__ float qs[64 * 33], ks[64 * 33], vs[64 * 33];
  __shared__ float ss[64 * 65];
  __shared__ int   rid[64];
  const int n = blockIdx.x, h = blockIdx.y, t = threadIdx.x;
  const int wi = n & 255, wh = wi >> 4, ww = wi & 15;
  const int base = (n * HEADS + h) * L_ * HD;

  const float4* q4 = reinterpret_cast<const float4*>(g_q + base);
  const float4* k4 = reinterpret_cast<const float4*>(g_k + base);
  const float4* v4 = reinterpret_cast<const float4*>(g_v + base);
  #pragma unroll
  for (int it = 0; it < 4; ++it) {
    int f = it * 128 + t;           // 512 f4
    int l = f >> 3, d = (f & 7) * 4;
    float4 a = q4[f], bq = k4[f], c = v4[f];
    qs[l*33+d] = a.x;  qs[l*33+d+1] = a.y;  qs[l*33+d+2] = a.z;  qs[l*33+d+3] = a.w;
    ks[l*33+d] = bq.x; ks[l*33+d+1] = bq.y; ks[l*33+d+2] = bq.z; ks[l*33+d+3] = bq.w;
    vs[l*33+d] = c.x;  vs[l*33+d+1] = c.y;  vs[l*33+d+2] = c.z;  vs[l*33+d+3] = c.w;
  }
  if (t < 64) {
    int r = t >> 3, c = t & 7;
    int hs = wh * WS_ + r, wsp = ww * WS_ + c;
    int ih = (hs  < 120) ? 0 : ((hs  < 124) ? 1 : 2);
    int iw = (wsp < 120) ? 0 : ((wsp < 124) ? 1 : 2);
    rid[t] = ih * 3 + iw;
  }
  __syncthreads();

  const int ry = t >> 3, cx = t & 7;  // 16x8 thread grid
  {
    float acc[4][8];
    #pragma unroll
    for (int i = 0; i < 4; ++i)
      #pragma unroll
      for (int j = 0; j < 8; ++j) acc[i][j] = 0.f;
    #pragma unroll 4
    for (int d = 0; d < 32; ++d) {
      float a[4], bb[8];
      #pragma unroll
      for (int i = 0; i < 4; ++i) a[i] = qs[(ry * 4 + i) * 33 + d];
      #pragma unroll
      for (int j = 0; j < 8; ++j) bb[j] = ks[(cx * 8 + j) * 33 + d];
      #pragma unroll
      for (int i = 0; i < 4; ++i)
        #pragma unroll
        for (int j = 0; j < 8; ++j) acc[i][j] += a[i] * bb[j];
    }
    #pragma unroll
    for (int i = 0; i < 4; ++i)
      #pragma unroll
      for (int j = 0; j < 8; ++j)
        ss[(ry * 4 + i) * 65 + cx * 8 + j] = acc[i][j];
  }
  __syncthreads();

  // softmax: warp per row, 2 cols per lane
  const int warp = t >> 5, lane = t & 31;
  const float* pb = prev + (size_t)(n * HEADS + h) * 4096;
  float* ab = attn_out ? attn_out + (size_t)(n * HEADS + h) * 4096 : nullptr;
  const int idk0 = rid[lane], idk1 = rid[lane + 32];
  for (int rr = 0; rr < 16; ++rr) {
    int row = warp * 16 + rr;
    int idq = rid[row];
    float v0 = ss[row * 65 + lane];
    float v1 = ss[row * 65 + lane + 32];
    v0 = fmaf(v0, SCALE, (idq == idk0) ? 0.f : -100.f) * pb[row * 64 + lane];
    v1 = fmaf(v1, SCALE, (idq == idk1) ? 0.f : -100.f) * pb[row * 64 + lane + 32];
    float mx = fmaxf(v0, v1);
    #pragma unroll
    for (int o = 16; o >= 1; o >>= 1) mx = fmaxf(mx, __shfl_xor_sync(0xffffffffu, mx, o));
    float e0 = __expf(v0 - mx), e1 = __expf(v1 - mx);
    float sum = e0 + e1;
    #pragma unroll
    for (int o = 16; o >= 1; o >>= 1) sum += __shfl_xor_sync(0xffffffffu, sum, o);
    float inv = 1.f / sum;
    e0 *= inv; e1 *= inv;
    ss[row * 65 + lane]      = e0;
    ss[row * 65 + lane + 32] = e1;
    if (ab) { ab[row * 64 + lane] = e0; ab[row * 64 + lane + 32] = e1; }
  }
  __syncthreads();

  // O = P @ V  (64x32, K=64); thread: 4 rows x 4 d
  {
    float acc[4][4];
    #pragma unroll
    for (int i = 0; i < 4; ++i)
      #pragma unroll
      for (int j = 0; j < 4; ++j) acc[i][j] = 0.f;
    #pragma unroll 4
    for (int kk = 0; kk < 64; ++kk) {
      float p[4], vv[4];
      #pragma unroll
      for (int i = 0; i < 4; ++i) p[i] = ss[(ry * 4 + i) * 65 + kk];
      #pragma unroll
      for (int j = 0; j < 4; ++j) vv[j] = vs[kk * 33 + cx * 4 + j];
      #pragma unroll
      for (int i = 0; i < 4; ++i)
        #pragma unroll
        for (int j = 0; j < 4; ++j) acc[i][j] += p[i] * vv[j];
    }
    #pragma unroll
    for (int i = 0; i < 4; ++i) {
      int l = ry * 4 + i;
      *reinterpret_cast<float4*>(&g_o[(n * L_ + l) * C_ + h * HD + cx * 4]) =
          make_float4(acc[i][0], acc[i][1], acc[i][2], acc[i][3]);
    }
  }
}

// ---------------------------------------------------------------------------
// Kernel 3: LePE + O, proj GEMM, window-reverse + unshift scatter.
// One block per window, 256 threads.
// ---------------------------------------------------------------------------
__global__ __launch_bounds__(256, 1) void lepe_proj_kernel(
    const float* __restrict__ proj_w, const float* __restrict__ proj_b,
    const float* __restrict__ lepe_w, const float* __restrict__ lepe_b,
    float* __restrict__ out) {
  extern __shared__ float sm[];
  float* vsm = sm;                   // [64][256]
  float* A   = sm + 64 * 256;        // [256][65]  (o + lepe, transposed)
  float* Bs  = A + 256 * 65;         // [256][64]
  const int n = blockIdx.x, t = threadIdx.x;
  const int b = n >> 8, wi = n & 255, wh = wi >> 4, ww = wi & 15;

  // V window into [l][c]
  const float4* v4 = reinterpret_cast<const float4*>(g_v + n * HEADS * L_ * HD);
  #pragma unroll
  for (int it = 0; it < 16; ++it) {
    int f = it * 256 + t;            // 4096 f4, [h][l][d4]
    int hh = f >> 9, rem = f & 511;
    int l = rem >> 3, d4 = rem & 7;
    *reinterpret_cast<float4*>(&vsm[l * C_ + hh * HD + d4 * 4]) = v4[f];
  }
  __syncthreads();

  // lepe (3x3 depthwise, window-local SAME) + o  -> A[c][l]
  {
    const int c = t;
    float w9[9];
    #pragma unroll
    for (int i = 0; i < 9; ++i) w9[i] = lepe_w[i * C_ + c];
    const float bl = lepe_b[c];
    const float* ob = g_o + n * L_ * C_;
    for (int l = 0; l < 64; ++l) {
      int r = l >> 3, cc = l & 7;
      float s = ob[l * C_ + c] + bl;
      #pragma unroll
      for (int dr = 0; dr < 3; ++dr) {
        int rr = r + dr - 1;
        if (rr < 0 || rr > 7) continue;
        #pragma unroll
        for (int dc = 0; dc < 3; ++dc) {
          int c2 = cc + dc - 1;
          if (c2 < 0 || c2 > 7) continue;
          s += w9[dr * 3 + dc] * vsm[(rr * 8 + c2) * C_ + c];
        }
      }
      A[c * 65 + l] = s;
    }
  }
  __syncthreads();

  // proj GEMM: 64x256, K=256, 4 chunks of 64 cols
  const int ty = t >> 4, tx = t & 15;
  const float4* pw4 = reinterpret_cast<const float4*>(proj_w);
  for (int ch = 0; ch < 4; ++ch) {
    #pragma unroll
    for (int it = 0; it < 16; ++it) {
      int f = it * 256 + t;
      int k = f >> 4, j4 = f & 15;
      *reinterpret_cast<float4*>(&Bs[k * 64 + j4 * 4]) = pw4[k * 64 + ch * 16 + j4];
    }
    __syncthreads();

    float acc[4][4];
    #pragma unroll
    for (int i = 0; i < 4; ++i)
      #pragma unroll
      for (int j = 0; j < 4; ++j) acc[i][j] = 0.f;

    #pragma unroll 8
    for (int k = 0; k < 256; ++k) {
      float a[4];
      #pragma unroll
      for (int i = 0; i < 4; ++i) a[i] = A[k * 65 + ty * 4 + i];
      float4 bv = *reinterpret_cast<const float4*>(&Bs[k * 64 + tx * 4]);
      float bb[4] = {bv.x, bv.y, bv.z, bv.w};
      #pragma unroll
      for (int i = 0; i < 4; ++i)
        #pragma unroll
        for (int j = 0; j < 4; ++j) acc[i][j] += a[i] * bb[j];
    }
    __syncthreads();

    const int co0 = ch * 64 + tx * 4;
    const float b0 = proj_b[co0 + 0], b1 = proj_b[co0 + 1];
    const float b2 = proj_b[co0 + 2], b3 = proj_b[co0 + 3];
    #pragma unroll
    for (int i = 0; i < 4; ++i) {
      int l = ty * 4 + i;
      int r = l >> 3, cc = l & 7;
      int hh = (wh * WS_ + r  + SHIFT) & 127;
      int wp = (ww * WS_ + cc + SHIFT) & 127;
      *reinterpret_cast<float4*>(&out[((b * H_ + hh) * W_ + wp) * C_ + co0]) =
          make_float4(acc[i][0] + b0, acc[i][1] + b1, acc[i][2] + b2, acc[i][3] + b3);
    }
  }
}

// ---------------------------------------------------------------------------
extern "C" void kernel_launch(void* const* d_in, const int* in_sizes, int n_in,
                              void* d_out, int out_size) {
  const float* x      = (const float*)d_in[0];
  const float* prev   = (const float*)d_in[1];
  const float* qkv_w  = (const float*)d_in[2];
  const float* qkv_b  = (const float*)d_in[3];
  const float* proj_w = (const float*)d_in[4];
  const float* proj_b = (const float*)d_in[5];
  const float* lepe_w = (const float*)d_in[6];
  const float* lepe_b = (const float*)d_in[7];
  float* out  = (float*)d_out;
  float* attn = (out_size > OUT_ELEMS) ? out + OUT_ELEMS : nullptr;

  const int smem1 = (256 * 65 + 256 * 64) * 4;               // 132096
  const int smem3 = (64 * 256 + 256 * 65 + 256 * 64) * 4;    // 197632
  cudaFuncSetAttribute(qkv_kernel, cudaFuncAttributeMaxDynamicSharedMemorySize, smem1);
  cudaFuncSetAttribute(lepe_proj_kernel, cudaFuncAttributeMaxDynamicSharedMemorySize, smem3);

  qkv_kernel<<<NWIN, 256, smem1>>>(x, qkv_w, qkv_b);
  attn_kernel<<<dim3(NWIN, HEADS), 128>>>(prev, attn);
  lepe_proj_kernel<<<NWIN, 256, smem3>>>(proj_w, proj_b, lepe_w, lepe_b, out);
}